// round 15
// baseline (speedup 1.0000x reference)
#include <cuda_runtime.h>
#include <cuda_bf16.h>
#include <math.h>

// Problem constants
#define NN   50000
#define FF   500
#define EE   1600000
#define PEE  400000
#define HH1  128
#define HH2  64

// Output layout (floats): res[800000] | lsm[150000] | att[150000] | feat[3200000]
#define OUT_RES  0
#define OUT_LSM  800000
#define OUT_ATT  950000
#define OUT_FEAT 1100000

#define KPAD1 512   // 500 padded
#define KPAD2 128

// ---------------------------------------------------------------------------
// Scratch (static __device__ arrays; allocation-free per harness rules)
__device__ int   g_degi[NN];
__device__ float g_dinv[NN];
__device__ int   g_off[NN + 1];
__device__ int   g_cursor[NN];
__device__ int   g_csr_src[EE];
__device__ float g_gW1[FF * HH1];
__device__ __nv_bfloat16 g_W1hT[HH1 * KPAD1];
__device__ __nv_bfloat16 g_W1lT[HH1 * KPAD1];
__device__ __nv_bfloat16 g_W2hT[HH2 * KPAD2];
__device__ __nv_bfloat16 g_W2lT[HH2 * KPAD2];
__device__ float g_h1pre[NN * HH1];   // dinv-scaled
__device__ float g_h1[NN * HH1];
__device__ float g_h2pre[NN * HH2];   // dinv-scaled
__device__ float g_headpre[NN * 6];   // dinv-scaled

// ---------------------------------------------------------------------------
__device__ __forceinline__ unsigned pack_bf16(float a, float b) {
    __nv_bfloat162 h = __floats2bfloat162_rn(a, b);
    return *(unsigned*)&h;
}
__device__ __forceinline__ float bf_hi(float v) {
    return __bfloat162float(__float2bfloat16(v));
}
__device__ __forceinline__ void mma16816(float* d, const unsigned* a,
                                         unsigned b0, unsigned b1) {
    asm volatile(
        "mma.sync.aligned.m16n8k16.row.col.f32.bf16.bf16.f32 "
        "{%0,%1,%2,%3},{%4,%5,%6,%7},{%8,%9},{%0,%1,%2,%3};\n"
        : "+f"(d[0]), "+f"(d[1]), "+f"(d[2]), "+f"(d[3])
        : "r"(a[0]), "r"(a[1]), "r"(a[2]), "r"(a[3]), "r"(b0), "r"(b1));
}
__device__ __forceinline__ void ldsm4(unsigned* r, unsigned addr) {
    asm volatile("ldmatrix.sync.aligned.m8n8.x4.shared.b16 {%0,%1,%2,%3}, [%4];"
                 : "=r"(r[0]), "=r"(r[1]), "=r"(r[2]), "=r"(r[3]) : "r"(addr));
}
__device__ __forceinline__ void cp16(unsigned daddr, const void* sptr) {
    asm volatile("cp.async.cg.shared.global [%0], [%1], 16;"
                 :: "r"(daddr), "l"(sptr) : "memory");
}
#define CP_COMMIT() asm volatile("cp.async.commit_group;" ::: "memory")
#define CP_WAIT0()  asm volatile("cp.async.wait_group 0;" ::: "memory")

// ---------------------------------------------------------------------------
// gW1 = glove @ W1   [FF x FF] @ [FF x HH1]
__global__ void k_glove_w1(const float* __restrict__ glove,
                           const float* __restrict__ W1,
                           float* __restrict__ gW1) {
    __shared__ float row[FF];
    int k = blockIdx.x;
    for (int f = threadIdx.x; f < FF; f += blockDim.x) row[f] = glove[k * FF + f];
    __syncthreads();
    int j = threadIdx.x;  // 128 threads
    float acc = 0.f;
    #pragma unroll 4
    for (int f = 0; f < FF; f++) acc += row[f] * __ldg(&W1[f * HH1 + j]);
    gW1[k * HH1 + j] = acc;
}

// Split weight W[KS x N] into transposed bf16 hi/lo [N x KP] (zero padded)
template <int KS, int KP, int NW>
__global__ void k_splitW(const float* __restrict__ W,
                         __nv_bfloat16* __restrict__ WhT,
                         __nv_bfloat16* __restrict__ WlT) {
    int idx = blockIdx.x * blockDim.x + threadIdx.x;
    if (idx >= NW * KP) return;
    int n = idx / KP, k = idx % KP;
    float v = (k < KS) ? __ldg(&W[(long)k * NW + n]) : 0.f;
    float h = bf_hi(v);
    WhT[idx] = __float2bfloat16(h);
    WlT[idx] = __float2bfloat16(v - h);
}

// ---------------------------------------------------------------------------
// degree / norm / CSR build
__global__ void k_deg_acc(const int* __restrict__ dst, int* __restrict__ degi) {
    int e = blockIdx.x * blockDim.x + threadIdx.x;
    if (e < EE) atomicAdd(&degi[dst[e]], 1);
}
__global__ void k_dinv(const int* __restrict__ degi, float* __restrict__ dinv) {
    int i = blockIdx.x * blockDim.x + threadIdx.x;
    if (i < NN) dinv[i] = rsqrtf((float)degi[i] + 1.0f);  // +1 self loop
}
__global__ void k_scan(const int* __restrict__ degi, int* __restrict__ off,
                       int* __restrict__ cursor) {
    __shared__ int warp_sums[32];
    __shared__ int s_carry;
    int tid = threadIdx.x, lane = tid & 31, wid = tid >> 5;
    if (tid == 0) s_carry = 0;
    __syncthreads();
    for (int base = 0; base < NN; base += 1024) {
        int idx = base + tid;
        int v = (idx < NN) ? degi[idx] : 0;
        int x = v;
        #pragma unroll
        for (int o = 1; o < 32; o <<= 1) {
            int y = __shfl_up_sync(0xffffffffu, x, o);
            if (lane >= o) x += y;
        }
        if (lane == 31) warp_sums[wid] = x;
        __syncthreads();
        if (wid == 0) {
            int s = warp_sums[lane];
            #pragma unroll
            for (int o = 1; o < 32; o <<= 1) {
                int y = __shfl_up_sync(0xffffffffu, s, o);
                if (lane >= o) s += y;
            }
            warp_sums[lane] = s;
        }
        __syncthreads();
        int carry = s_carry;
        int woff = wid ? warp_sums[wid - 1] : 0;
        int excl = carry + woff + (x - v);
        if (idx < NN) { off[idx] = excl; cursor[idx] = excl; }
        __syncthreads();
        if (tid == 0) s_carry = carry + warp_sums[31];
        __syncthreads();
    }
    if (threadIdx.x == 0) off[NN] = s_carry;
}
__global__ void k_fill(const int* __restrict__ src, const int* __restrict__ dst,
                       int* __restrict__ cursor, int* __restrict__ csr_src) {
    int e = blockIdx.x * blockDim.x + threadIdx.x;
    if (e >= EE) return;
    int d = dst[e];
    int p = atomicAdd(&cursor[d], 1);
    csr_src[p] = src[e];
}

// ---------------------------------------------------------------------------
// Pipelined bf16-split tensor GEMM with ldmatrix + cp.async double buffering.
// C[M x BN] = rowscale[m] * (A[M x KSRC] @ B)  (B split hi/lo, [BN x KP])
// BM=128, BK=32, 256 threads (8 warps, 4x2 warp grid). RELU applied to A on load.
// MMA issue order is term-major per p-block: same-accumulator reuse distance 4
// (was 1) to break HMMA RAW chains.
template <int BN, int KSRC, int KP, bool RELU>
__global__ void __launch_bounds__(256)
k_mma(const float* __restrict__ A,
      const __nv_bfloat16* __restrict__ BhT, const __nv_bfloat16* __restrict__ BlT,
      const float* __restrict__ rowscale, float* __restrict__ C, int M) {
    constexpr int BM = 128, BK = 32, BKP = 40;
    constexpr int WN = (BN == 128) ? 64 : 32;
    constexpr int NF = WN / 8;
    constexpr int A_SZ = BM * BKP;          // elems per A buffer
    constexpr int B_SZ = BN * BKP;
    constexpr int STAGE = 2 * A_SZ + 2 * B_SZ;
    constexpr int T = KP / BK;

    extern __shared__ __align__(16) __nv_bfloat16 sm[];
    unsigned smb = (unsigned)__cvta_generic_to_shared(sm);

    int tid = threadIdx.x;
    int m0 = blockIdx.x * BM;
    int lane = tid & 31, w = tid >> 5;
    int wm = (w >> 1) * 32, wn = (w & 1) * WN;
    int g = lane >> 2, tg = lane & 3;
    int l8 = lane & 7, sub = lane >> 3;
    // ldmatrix per-lane fragment byte offset within a buffer
    unsigned fo2 = ((((sub & 1) * 8 + l8) * BKP) + (sub >> 1) * 8) * 2;

    float acc[2][NF][4];
    #pragma unroll
    for (int mi = 0; mi < 2; mi++)
        #pragma unroll
        for (int ni = 0; ni < NF; ni++)
            #pragma unroll
            for (int q = 0; q < 4; q++) acc[mi][ni][q] = 0.f;

    int ar = tid >> 1;
    int ac0 = (tid & 1) * 16;
    long gr = m0 + ar;
    const float4* ap = (const float4*)(A + gr * (long)KSRC);

    // --- helpers -----------------------------------------------------------
    auto copyB = [&](int s, int kc) {
        unsigned bhB = smb + (s * STAGE + 2 * A_SZ) * 2;
        unsigned blB = bhB + B_SZ * 2;
        for (int idx = tid; idx < BN * 4; idx += 256) {
            int n = idx >> 2, ko = (idx & 3) * 8;
            unsigned doff = (n * BKP + ko) * 2;
            cp16(bhB + doff, BhT + (long)n * KP + kc + ko);
            cp16(blB + doff, BlT + (long)n * KP + kc + ko);
        }
    };
    auto loadA = [&](float4* pv, int kc) {
        #pragma unroll
        for (int j = 0; j < 4; j++) {
            int c = kc + ac0 + j * 4;
            float4 v = make_float4(0.f, 0.f, 0.f, 0.f);
            if (gr < M && c < KSRC) v = __ldg(ap + (c >> 2));
            if (RELU) {
                v.x = fmaxf(v.x, 0.f); v.y = fmaxf(v.y, 0.f);
                v.z = fmaxf(v.z, 0.f); v.w = fmaxf(v.w, 0.f);
            }
            pv[j] = v;
        }
    };
    auto stsA = [&](int s, const float4* pv) {
        __nv_bfloat16* AhS = sm + s * STAGE;
        __nv_bfloat16* AlS = AhS + A_SZ;
        #pragma unroll
        for (int j = 0; j < 4; j++) {
            float4 v = pv[j];
            float h0 = bf_hi(v.x), h1 = bf_hi(v.y), h2 = bf_hi(v.z), h3 = bf_hi(v.w);
            int lc = ac0 + j * 4;
            uint2 hh; hh.x = pack_bf16(h0, h1); hh.y = pack_bf16(h2, h3);
            uint2 ll; ll.x = pack_bf16(v.x - h0, v.y - h1);
            ll.y = pack_bf16(v.z - h2, v.w - h3);
            *(uint2*)(AhS + ar * BKP + lc) = hh;
            *(uint2*)(AlS + ar * BKP + lc) = ll;
        }
    };
    auto compute = [&](int s) {
        unsigned base = smb + s * STAGE * 2;
        unsigned ahB = base, alB = base + A_SZ * 2;
        unsigned bhB = base + 2 * A_SZ * 2, blB = bhB + B_SZ * 2;
        #pragma unroll
        for (int ks = 0; ks < 2; ks++) {
            int kb = ks * 16;
            unsigned ah[2][4], al[2][4];
            #pragma unroll
            for (int mi = 0; mi < 2; mi++) {
                unsigned ro = ((wm + mi * 16) * BKP + kb) * 2 + fo2;
                ldsm4(ah[mi], ahB + ro);
                ldsm4(al[mi], alB + ro);
            }
            #pragma unroll
            for (int p = 0; p < NF / 2; p++) {
                unsigned bo = ((wn + p * 16) * BKP + kb) * 2 + fo2;
                unsigned bh[4], bl[4];
                ldsm4(bh, bhB + bo);
                ldsm4(bl, blB + bo);
                // term 1: Ah * Bh  (4 independent accumulators)
                mma16816(acc[0][2 * p],     ah[0], bh[0], bh[2]);
                mma16816(acc[1][2 * p],     ah[1], bh[0], bh[2]);
                mma16816(acc[0][2 * p + 1], ah[0], bh[1], bh[3]);
                mma16816(acc[1][2 * p + 1], ah[1], bh[1], bh[3]);
                // term 2: Ah * Bl
                mma16816(acc[0][2 * p],     ah[0], bl[0], bl[2]);
                mma16816(acc[1][2 * p],     ah[1], bl[0], bl[2]);
                mma16816(acc[0][2 * p + 1], ah[0], bl[1], bl[3]);
                mma16816(acc[1][2 * p + 1], ah[1], bl[1], bl[3]);
                // term 3: Al * Bh
                mma16816(acc[0][2 * p],     al[0], bh[0], bh[2]);
                mma16816(acc[1][2 * p],     al[1], bh[0], bh[2]);
                mma16816(acc[0][2 * p + 1], al[0], bh[1], bh[3]);
                mma16816(acc[1][2 * p + 1], al[1], bh[1], bh[3]);
            }
        }
    };

    // --- prologue: fill stage 0 -------------------------------------------
    copyB(0, 0);
    CP_COMMIT();
    {
        float4 pv[4];
        loadA(pv, 0);
        stsA(0, pv);
    }

    // --- main pipeline -----------------------------------------------------
    #pragma unroll 1
    for (int i = 0; i < T; i++) {
        int s = i & 1;
        CP_WAIT0();
        __syncthreads();
        float4 pv2[4];
        if (i + 1 < T) {
            copyB(s ^ 1, (i + 1) * BK);
            CP_COMMIT();
            loadA(pv2, (i + 1) * BK);
        }
        compute(s);
        if (i + 1 < T) stsA(s ^ 1, pv2);
    }

    // --- epilogue: write rowscale * result --------------------------------
    #pragma unroll
    for (int mi = 0; mi < 2; mi++) {
        int r0 = m0 + wm + mi * 16 + g;
        float s0 = (r0 < M) ? __ldg(&rowscale[r0]) : 0.f;
        float s1 = (r0 + 8 < M) ? __ldg(&rowscale[r0 + 8]) : 0.f;
        #pragma unroll
        for (int ni = 0; ni < NF; ni++) {
            int c = wn + ni * 8 + 2 * tg;
            if (r0 < M)
                *(float2*)&C[(long)r0 * BN + c] =
                    make_float2(s0 * acc[mi][ni][0], s0 * acc[mi][ni][1]);
            if (r0 + 8 < M)
                *(float2*)&C[(long)(r0 + 8) * BN + c] =
                    make_float2(s1 * acc[mi][ni][2], s1 * acc[mi][ni][3]);
        }
    }
}

// ---------------------------------------------------------------------------
// CSR aggregation. pre rows are PRE-SCALED by dinv[src].
// out[d] = b + dinv[d]*(sum_s pre[s] + pre[d])
// DIM=128: warp per node. Dual accumulators, 2 edges/iter for 2x MLP.
__global__ void k_agg128(const float* __restrict__ pre, const int* __restrict__ off,
                         const int* __restrict__ csr_src, const float* __restrict__ dinv,
                         const float* __restrict__ bias, float* __restrict__ out) {
    int t = blockIdx.x * blockDim.x + threadIdx.x;
    int node = t >> 5, lane = t & 31;
    if (node >= NN) return;
    int beg = __ldg(&off[node]), end = __ldg(&off[node + 1]);
    const float4* p4 = (const float4*)pre;
    float4 a0 = make_float4(0.f, 0.f, 0.f, 0.f);
    float4 a1 = make_float4(0.f, 0.f, 0.f, 0.f);
    int i = beg;
    for (; i + 1 < end; i += 2) {
        int s0 = __ldg(&csr_src[i]);
        int s1 = __ldg(&csr_src[i + 1]);
        float4 v0 = __ldg(p4 + (long)s0 * 32 + lane);
        float4 v1 = __ldg(p4 + (long)s1 * 32 + lane);
        a0.x += v0.x; a0.y += v0.y; a0.z += v0.z; a0.w += v0.w;
        a1.x += v1.x; a1.y += v1.y; a1.z += v1.z; a1.w += v1.w;
    }
    if (i < end) {
        int s0 = __ldg(&csr_src[i]);
        float4 v0 = __ldg(p4 + (long)s0 * 32 + lane);
        a0.x += v0.x; a0.y += v0.y; a0.z += v0.z; a0.w += v0.w;
    }
    float wd = __ldg(&dinv[node]);
    float4 sv = __ldg(p4 + (long)node * 32 + lane);
    float4 b = __ldg((const float4*)bias + lane);
    float4 o;
    o.x = b.x + wd * (a0.x + a1.x + sv.x);
    o.y = b.y + wd * (a0.y + a1.y + sv.y);
    o.z = b.z + wd * (a0.z + a1.z + sv.z);
    o.w = b.w + wd * (a0.w + a1.w + sv.w);
    *((float4*)out + (long)node * 32 + lane) = o;
}

// DIM=64: half-warp per node + FUSED heads GEMM. Dual accumulators.
__global__ void k_agg64h(const float* __restrict__ pre, const int* __restrict__ off,
                         const int* __restrict__ csr_src, const float* __restrict__ dinv,
                         const float* __restrict__ bias,
                         const float* __restrict__ W_attr, const float* __restrict__ W_attk,
                         float* __restrict__ out, float* __restrict__ headpre) {
    __shared__ float Ws[HH2 * 6];   // [k][c] layout
    for (int i = threadIdx.x; i < HH2 * 6; i += blockDim.x) {
        int k = i / 6, c = i % 6;
        Ws[i] = (c < 3) ? __ldg(&W_attr[k * 3 + c]) : __ldg(&W_attk[k * 3 + (c - 3)]);
    }
    __syncthreads();
    int t = blockIdx.x * blockDim.x + threadIdx.x;
    int node = t >> 4, lane = t & 15;
    if (node >= NN) return;
    int beg = __ldg(&off[node]), end = __ldg(&off[node + 1]);
    const float4* p4 = (const float4*)pre;
    float4 a0 = make_float4(0.f, 0.f, 0.f, 0.f);
    float4 a1 = make_float4(0.f, 0.f, 0.f, 0.f);
    int i = beg;
    for (; i + 1 < end; i += 2) {
        int s0 = __ldg(&csr_src[i]);
        int s1 = __ldg(&csr_src[i + 1]);
        float4 v0 = __ldg(p4 + (long)s0 * 16 + lane);
        float4 v1 = __ldg(p4 + (long)s1 * 16 + lane);
        a0.x += v0.x; a0.y += v0.y; a0.z += v0.z; a0.w += v0.w;
        a1.x += v1.x; a1.y += v1.y; a1.z += v1.z; a1.w += v1.w;
    }
    if (i < end) {
        int s0 = __ldg(&csr_src[i]);
        float4 v0 = __ldg(p4 + (long)s0 * 16 + lane);
        a0.x += v0.x; a0.y += v0.y; a0.z += v0.z; a0.w += v0.w;
    }
    float wd = __ldg(&dinv[node]);
    float4 sv = __ldg(p4 + (long)node * 16 + lane);
    float4 b = __ldg((const float4*)bias + lane);
    float4 o;
    o.x = b.x + wd * (a0.x + a1.x + sv.x);
    o.y = b.y + wd * (a0.y + a1.y + sv.y);
    o.z = b.z + wd * (a0.z + a1.z + sv.z);
    o.w = b.w + wd * (a0.w + a1.w + sv.w);
    *((float4*)out + (long)node * 16 + lane) = o;

    // heads: this lane holds features [4*lane, 4*lane+4) of the node's row
    int k0 = lane * 4;
    float h[6];
    #pragma unroll
    for (int c = 0; c < 6; c++)
        h[c] = o.x * Ws[(k0 + 0) * 6 + c] + o.y * Ws[(k0 + 1) * 6 + c]
             + o.z * Ws[(k0 + 2) * 6 + c] + o.w * Ws[(k0 + 3) * 6 + c];
    #pragma unroll
    for (int sh = 8; sh; sh >>= 1)
        #pragma unroll
        for (int c = 0; c < 6; c++)
            h[c] += __shfl_down_sync(0xffffffffu, h[c], sh, 16);
    if (lane == 0) {
        float2* hp = (float2*)(headpre + (long)node * 6);
        hp[0] = make_float2(wd * h[0], wd * h[1]);
        hp[1] = make_float2(wd * h[2], wd * h[3]);
        hp[2] = make_float2(wd * h[4], wd * h[5]);
    }
}

// DIM=6 heads + fused bias + log_softmax + att. pre rows pre-scaled.
__global__ void k_agg6(const float* __restrict__ pre, const int* __restrict__ off,
                       const int* __restrict__ csr_src, const float* __restrict__ dinv,
                       const float* __restrict__ b_attr, const float* __restrict__ b_attk,
                       float* __restrict__ out) {
    int t = blockIdx.x * blockDim.x + threadIdx.x;
    int node = t >> 5, lane = t & 31;
    if (node >= NN) return;
    int beg = __ldg(&off[node]), end = __ldg(&off[node + 1]);
    float a[6] = {0.f, 0.f, 0.f, 0.f, 0.f, 0.f};
    for (int i = beg + lane; i < end; i += 32) {
        int s = __ldg(&csr_src[i]);
        const float2* p = (const float2*)(pre + (long)s * 6);
        float2 p0 = __ldg(p), p1 = __ldg(p + 1), p2 = __ldg(p + 2);
        a[0] += p0.x; a[1] += p0.y;
        a[2] += p1.x; a[3] += p1.y;
        a[4] += p2.x; a[5] += p2.y;
    }
    #pragma unroll
    for (int o = 16; o; o >>= 1)
        #pragma unroll
        for (int c = 0; c < 6; c++) a[c] += __shfl_down_sync(0xffffffffu, a[c], o);
    if (lane == 0) {
        float wd = __ldg(&dinv[node]);
        const float2* p = (const float2*)(pre + (long)node * 6);
        float2 p0 = __ldg(p), p1 = __ldg(p + 1), p2 = __ldg(p + 2);
        float v0 = b_attr[0] + wd * (a[0] + p0.x);
        float v1 = b_attr[1] + wd * (a[1] + p0.y);
        float v2 = b_attr[2] + wd * (a[2] + p1.x);
        float v3 = b_attk[0] + wd * (a[3] + p1.y);
        float v4 = b_attk[1] + wd * (a[4] + p2.x);
        float v5 = b_attk[2] + wd * (a[5] + p2.y);
        float m = fmaxf(v0, fmaxf(v1, v2));
        float l = m + logf(expf(v0 - m) + expf(v1 - m) + expf(v2 - m));
        out[OUT_LSM + node * 3 + 0] = v0 - l;
        out[OUT_LSM + node * 3 + 1] = v1 - l;
        out[OUT_LSM + node * 3 + 2] = v2 - l;
        out[OUT_ATT + node * 3 + 0] = v3;
        out[OUT_ATT + node * 3 + 1] = v4;
        out[OUT_ATT + node * 3 + 2] = v5;
    }
}

// edge scores: res[e] = dot(feat[i], feat[j]), 8 lanes/edge
__global__ void k_edge_scores(const float* __restrict__ feat,
                              const int* __restrict__ pos,
                              const int* __restrict__ neg,
                              float* __restrict__ res) {
    int t = blockIdx.x * blockDim.x + threadIdx.x;
    int e = t >> 3, l = t & 7;
    if (e >= 2 * PEE) return;
    int a, b;
    if (e < PEE) { a = __ldg(pos + e); b = __ldg(pos + PEE + e); }
    else         { a = __ldg(neg + (e - PEE)); b = __ldg(neg + PEE + (e - PEE)); }
    const float4* fa = (const float4*)(feat + (long)a * 64);
    const float4* fb = (const float4*)(feat + (long)b * 64);
    float4 u = __ldg(fa + l), v = __ldg(fb + l);
    float s = u.x * v.x + u.y * v.y + u.z * v.z + u.w * v.w;
    u = __ldg(fa + l + 8); v = __ldg(fb + l + 8);
    s += u.x * v.x + u.y * v.y + u.z * v.z + u.w * v.w;
    s += __shfl_down_sync(0xffffffffu, s, 4, 8);
    s += __shfl_down_sync(0xffffffffu, s, 2, 8);
    s += __shfl_down_sync(0xffffffffu, s, 1, 8);
    if (l == 0) res[e] = s;
}

// ---------------------------------------------------------------------------
static inline int cdiv(long a, int b) { return (int)((a + b - 1) / b); }

// dynamic smem: (2*A + 2*B) per stage * 2 stages * 2 bytes
#define SMEM1 ((2 * 128 * 40 + 2 * 128 * 40) * 2 * 2)   // 81920
#define SMEM2 ((2 * 128 * 40 + 2 * 64 * 40) * 2 * 2)    // 61440

extern "C" void kernel_launch(void* const* d_in, const int* in_sizes, int n_in,
                              void* d_out, int out_size) {
    const float* x      = (const float*)d_in[0];
    const float* glove  = (const float*)d_in[1];
    const float* W1     = (const float*)d_in[2];
    const float* b1     = (const float*)d_in[3];
    const float* W2     = (const float*)d_in[4];
    const float* b2     = (const float*)d_in[5];
    const float* W_attr = (const float*)d_in[6];
    const float* b_attr = (const float*)d_in[7];
    const float* W_attk = (const float*)d_in[8];
    const float* b_attk = (const float*)d_in[9];
    const int* edge     = (const int*)d_in[10];
    const int* pos      = (const int*)d_in[11];
    const int* neg      = (const int*)d_in[12];
    float* out = (float*)d_out;

    const int* e_src = edge;
    const int* e_dst = edge + EE;

    int *degi, *off, *cursor, *csr_src;
    float *dinv, *gW1, *h1pre, *h1, *h2pre, *headpre;
    __nv_bfloat16 *W1hT, *W1lT, *W2hT, *W2lT;
    cudaGetSymbolAddress((void**)&degi,    g_degi);
    cudaGetSymbolAddress((void**)&dinv,    g_dinv);
    cudaGetSymbolAddress((void**)&off,     g_off);
    cudaGetSymbolAddress((void**)&cursor,  g_cursor);
    cudaGetSymbolAddress((void**)&csr_src, g_csr_src);
    cudaGetSymbolAddress((void**)&gW1,     g_gW1);
    cudaGetSymbolAddress((void**)&W1hT,    g_W1hT);
    cudaGetSymbolAddress((void**)&W1lT,    g_W1lT);
    cudaGetSymbolAddress((void**)&W2hT,    g_W2hT);
    cudaGetSymbolAddress((void**)&W2lT,    g_W2lT);
    cudaGetSymbolAddress((void**)&h1pre,   g_h1pre);
    cudaGetSymbolAddress((void**)&h1,      g_h1);
    cudaGetSymbolAddress((void**)&h2pre,   g_h2pre);
    cudaGetSymbolAddress((void**)&headpre, g_headpre);

    float* feat = out + OUT_FEAT;

    cudaFuncSetAttribute(k_mma<HH1, FF, KPAD1, false>,
                         cudaFuncAttributeMaxDynamicSharedMemorySize, SMEM1);
    cudaFuncSetAttribute(k_mma<HH2, HH1, KPAD2, true>,
                         cudaFuncAttributeMaxDynamicSharedMemorySize, SMEM2);

    cudaMemsetAsync(degi, 0, NN * sizeof(int));

    // degree/dinv first (GEMM epilogues consume dinv)
    k_deg_acc<<<cdiv(EE, 256), 256>>>(e_dst, degi);
    k_dinv<<<cdiv(NN, 256), 256>>>(degi, dinv);

    // weights prep
    k_glove_w1<<<FF, HH1>>>(glove, W1, gW1);
    k_splitW<FF, KPAD1, HH1><<<cdiv((long)HH1 * KPAD1, 256), 256>>>(gW1, W1hT, W1lT);

    // GEMM1: h1pre = dinv .* (x @ gW1)
    k_mma<HH1, FF, KPAD1, false><<<cdiv(NN, 128), 256, SMEM1>>>(x, W1hT, W1lT,
                                                                dinv, h1pre, NN);

    // CSR build
    k_scan<<<1, 1024>>>(degi, off, cursor);
    k_fill<<<cdiv(EE, 256), 256>>>(e_src, e_dst, cursor, csr_src);

    // layer 1 aggregate (bias + self-loop fused; rows pre-scaled)
    k_agg128<<<cdiv((long)NN * 32, 256), 256>>>(h1pre, off, csr_src, dinv, b1, h1);

    // GEMM2: h2pre = dinv .* (relu(h1) @ W2)
    k_splitW<KPAD2, KPAD2, HH2><<<cdiv((long)HH2 * KPAD2, 256), 256>>>(W2, W2hT, W2lT);
    k_mma<HH2, HH1, KPAD2, true><<<cdiv(NN, 128), 256, SMEM2>>>(h1, W2hT, W2lT,
                                                                dinv, h2pre, NN);

    // layer 2 aggregate + FUSED heads GEMM (headpre dinv-scaled on write)
    k_agg64h<<<cdiv((long)NN * 16, 256), 256>>>(h2pre, off, csr_src, dinv, b2,
                                                W_attr, W_attk, feat, headpre);

    // heads aggregate + log_softmax + att fused
    k_agg6<<<cdiv((long)NN * 32, 256), 256>>>(headpre, off, csr_src, dinv,
                                              b_attr, b_attk, out);

    // edge dot-product scores
    k_edge_scores<<<cdiv((long)2 * PEE * 8, 256), 256>>>(feat, pos, neg, out + OUT_RES);
}

// round 17
// speedup vs baseline: 1.1057x; 1.1057x over previous
#include <cuda_runtime.h>
#include <cuda_fp16.h>
#include <math.h>

// Problem constants
#define NN   50000
#define FF   500
#define EE   1600000
#define PEE  400000
#define HH1  128
#define HH2  64

// Output layout (floats): res[800000] | lsm[150000] | att[150000] | feat[3200000]
#define OUT_RES  0
#define OUT_LSM  800000
#define OUT_ATT  950000
#define OUT_FEAT 1100000

#define KPAD1 512   // 500 padded
#define KPAD2 128

// ---------------------------------------------------------------------------
// Scratch (static __device__ arrays; allocation-free per harness rules)
__device__ int    g_degi[NN];
__device__ float  g_dinv[NN];
__device__ int    g_off[NN + 1];
__device__ int    g_cursor[NN];
__device__ int    g_csr_src[EE];
__device__ float  g_gW1[FF * HH1];
__device__ __half g_W1T[HH1 * KPAD1];
__device__ __half g_W2T[HH2 * KPAD2];
__device__ float  g_h1pre[NN * HH1];   // dinv-scaled
__device__ float  g_h1[NN * HH1];
__device__ float  g_h2pre[NN * HH2];   // dinv-scaled
__device__ float  g_headpre[NN * 6];   // dinv-scaled

// ---------------------------------------------------------------------------
__device__ __forceinline__ unsigned pack_f16(float a, float b) {
    __half2 h = __floats2half2_rn(a, b);
    return *(unsigned*)&h;
}
__device__ __forceinline__ float f16_hi(float v) {
    return __half2float(__float2half_rn(v));
}
__device__ __forceinline__ void mma16816(float* d, const unsigned* a,
                                         unsigned b0, unsigned b1) {
    asm volatile(
        "mma.sync.aligned.m16n8k16.row.col.f32.f16.f16.f32 "
        "{%0,%1,%2,%3},{%4,%5,%6,%7},{%8,%9},{%0,%1,%2,%3};\n"
        : "+f"(d[0]), "+f"(d[1]), "+f"(d[2]), "+f"(d[3])
        : "r"(a[0]), "r"(a[1]), "r"(a[2]), "r"(a[3]), "r"(b0), "r"(b1));
}
__device__ __forceinline__ void ldsm4(unsigned* r, unsigned addr) {
    asm volatile("ldmatrix.sync.aligned.m8n8.x4.shared.b16 {%0,%1,%2,%3}, [%4];"
                 : "=r"(r[0]), "=r"(r[1]), "=r"(r[2]), "=r"(r[3]) : "r"(addr));
}
__device__ __forceinline__ void cp16(unsigned daddr, const void* sptr) {
    asm volatile("cp.async.cg.shared.global [%0], [%1], 16;"
                 :: "r"(daddr), "l"(sptr) : "memory");
}
#define CP_COMMIT() asm volatile("cp.async.commit_group;" ::: "memory")
#define CP_WAIT0()  asm volatile("cp.async.wait_group 0;" ::: "memory")

// ---------------------------------------------------------------------------
// gW1 = glove @ W1   [FF x FF] @ [FF x HH1]
__global__ void k_glove_w1(const float* __restrict__ glove,
                           const float* __restrict__ W1,
                           float* __restrict__ gW1) {
    __shared__ float row[FF];
    int k = blockIdx.x;
    for (int f = threadIdx.x; f < FF; f += blockDim.x) row[f] = glove[k * FF + f];
    __syncthreads();
    int j = threadIdx.x;  // 128 threads
    float acc = 0.f;
    #pragma unroll 4
    for (int f = 0; f < FF; f++) acc += row[f] * __ldg(&W1[f * HH1 + j]);
    gW1[k * HH1 + j] = acc;
}

// Split weight W[KS x N] into transposed fp16 [N x KP] (zero padded)
template <int KS, int KP, int NW>
__global__ void k_splitW(const float* __restrict__ W, __half* __restrict__ WT) {
    int idx = blockIdx.x * blockDim.x + threadIdx.x;
    if (idx >= NW * KP) return;
    int n = idx / KP, k = idx % KP;
    float v = (k < KS) ? __ldg(&W[(long)k * NW + n]) : 0.f;
    WT[idx] = __float2half_rn(v);
}

// ---------------------------------------------------------------------------
// degree / norm / CSR build
__global__ void k_deg_acc(const int* __restrict__ dst, int* __restrict__ degi) {
    int e = blockIdx.x * blockDim.x + threadIdx.x;
    if (e < EE) atomicAdd(&degi[dst[e]], 1);
}
__global__ void k_dinv(const int* __restrict__ degi, float* __restrict__ dinv) {
    int i = blockIdx.x * blockDim.x + threadIdx.x;
    if (i < NN) dinv[i] = rsqrtf((float)degi[i] + 1.0f);  // +1 self loop
}
__global__ void k_scan(const int* __restrict__ degi, int* __restrict__ off,
                       int* __restrict__ cursor) {
    __shared__ int warp_sums[32];
    __shared__ int s_carry;
    int tid = threadIdx.x, lane = tid & 31, wid = tid >> 5;
    if (tid == 0) s_carry = 0;
    __syncthreads();
    for (int base = 0; base < NN; base += 1024) {
        int idx = base + tid;
        int v = (idx < NN) ? degi[idx] : 0;
        int x = v;
        #pragma unroll
        for (int o = 1; o < 32; o <<= 1) {
            int y = __shfl_up_sync(0xffffffffu, x, o);
            if (lane >= o) x += y;
        }
        if (lane == 31) warp_sums[wid] = x;
        __syncthreads();
        if (wid == 0) {
            int s = warp_sums[lane];
            #pragma unroll
            for (int o = 1; o < 32; o <<= 1) {
                int y = __shfl_up_sync(0xffffffffu, s, o);
                if (lane >= o) s += y;
            }
            warp_sums[lane] = s;
        }
        __syncthreads();
        int carry = s_carry;
        int woff = wid ? warp_sums[wid - 1] : 0;
        int excl = carry + woff + (x - v);
        if (idx < NN) { off[idx] = excl; cursor[idx] = excl; }
        __syncthreads();
        if (tid == 0) s_carry = carry + warp_sums[31];
        __syncthreads();
    }
    if (threadIdx.x == 0) off[NN] = s_carry;
}
__global__ void k_fill(const int* __restrict__ src, const int* __restrict__ dst,
                       int* __restrict__ cursor, int* __restrict__ csr_src) {
    int e = blockIdx.x * blockDim.x + threadIdx.x;
    if (e >= EE) return;
    int d = dst[e];
    int p = atomicAdd(&cursor[d], 1);
    csr_src[p] = src[e];
}

// ---------------------------------------------------------------------------
// Pipelined asymmetric-fp16 tensor GEMM (ldmatrix + cp.async double buffer).
// C[M x BN] = rowscale[m] * (A[M x KSRC] @ B)
// A split into fp16 hi+lo (2 terms, ~2^-22); B single fp16 (~2^-12).
// BM=128, BK=32, 256 threads (8 warps, 4x2 warp grid). RELU fused on A load.
template <int BN, int KSRC, int KP, bool RELU>
__global__ void __launch_bounds__(256)
k_mma(const float* __restrict__ A, const __half* __restrict__ BT,
      const float* __restrict__ rowscale, float* __restrict__ C, int M) {
    constexpr int BM = 128, BK = 32, BKP = 40;
    constexpr int WN = (BN == 128) ? 64 : 32;
    constexpr int NF = WN / 8;
    constexpr int A_SZ = BM * BKP;          // elems per A buffer
    constexpr int B_SZ = BN * BKP;
    constexpr int STAGE = 2 * A_SZ + B_SZ;
    constexpr int T = KP / BK;

    extern __shared__ __align__(16) __half sm[];
    unsigned smb = (unsigned)__cvta_generic_to_shared(sm);

    int tid = threadIdx.x;
    int m0 = blockIdx.x * BM;
    int lane = tid & 31, w = tid >> 5;
    int wm = (w >> 1) * 32, wn = (w & 1) * WN;
    int g = lane >> 2, tg = lane & 3;
    int l8 = lane & 7, sub = lane >> 3;
    unsigned fo2 = ((((sub & 1) * 8 + l8) * BKP) + (sub >> 1) * 8) * 2;

    float acc[2][NF][4];
    #pragma unroll
    for (int mi = 0; mi < 2; mi++)
        #pragma unroll
        for (int ni = 0; ni < NF; ni++)
            #pragma unroll
            for (int q = 0; q < 4; q++) acc[mi][ni][q] = 0.f;

    int ar = tid >> 1;
    int ac0 = (tid & 1) * 16;
    long gr = m0 + ar;
    const float4* ap = (const float4*)(A + gr * (long)KSRC);

    // --- helpers -----------------------------------------------------------
    auto copyB = [&](int s, int kc) {
        unsigned bB = smb + (s * STAGE + 2 * A_SZ) * 2;
        for (int idx = tid; idx < BN * 4; idx += 256) {
            int n = idx >> 2, ko = (idx & 3) * 8;
            cp16(bB + (n * BKP + ko) * 2, BT + (long)n * KP + kc + ko);
        }
    };
    auto loadA = [&](float4* pv, int kc) {
        #pragma unroll
        for (int j = 0; j < 4; j++) {
            int c = kc + ac0 + j * 4;
            float4 v = make_float4(0.f, 0.f, 0.f, 0.f);
            if (gr < M && c < KSRC) v = __ldg(ap + (c >> 2));
            if (RELU) {
                v.x = fmaxf(v.x, 0.f); v.y = fmaxf(v.y, 0.f);
                v.z = fmaxf(v.z, 0.f); v.w = fmaxf(v.w, 0.f);
            }
            pv[j] = v;
        }
    };
    auto stsA = [&](int s, const float4* pv) {
        __half* AhS = sm + s * STAGE;
        __half* AlS = AhS + A_SZ;
        #pragma unroll
        for (int j = 0; j < 4; j++) {
            float4 v = pv[j];
            float h0 = f16_hi(v.x), h1 = f16_hi(v.y), h2 = f16_hi(v.z), h3 = f16_hi(v.w);
            int lc = ac0 + j * 4;
            uint2 hh; hh.x = pack_f16(h0, h1); hh.y = pack_f16(h2, h3);
            uint2 ll; ll.x = pack_f16(v.x - h0, v.y - h1);
            ll.y = pack_f16(v.z - h2, v.w - h3);
            *(uint2*)(AhS + ar * BKP + lc) = hh;
            *(uint2*)(AlS + ar * BKP + lc) = ll;
        }
    };
    auto compute = [&](int s) {
        unsigned base = smb + s * STAGE * 2;
        unsigned ahB = base, alB = base + A_SZ * 2;
        unsigned bB = base + 2 * A_SZ * 2;
        #pragma unroll
        for (int ks = 0; ks < 2; ks++) {
            int kb = ks * 16;
            unsigned ah[2][4], al[2][4];
            #pragma unroll
            for (int mi = 0; mi < 2; mi++) {
                unsigned ro = ((wm + mi * 16) * BKP + kb) * 2 + fo2;
                ldsm4(ah[mi], ahB + ro);
                ldsm4(al[mi], alB + ro);
            }
            #pragma unroll
            for (int p = 0; p < NF / 2; p++) {
                unsigned bo = ((wn + p * 16) * BKP + kb) * 2 + fo2;
                unsigned bh[4];
                ldsm4(bh, bB + bo);
                // term 1: Ah * B
                mma16816(acc[0][2 * p],     ah[0], bh[0], bh[2]);
                mma16816(acc[1][2 * p],     ah[1], bh[0], bh[2]);
                mma16816(acc[0][2 * p + 1], ah[0], bh[1], bh[3]);
                mma16816(acc[1][2 * p + 1], ah[1], bh[1], bh[3]);
                // term 2: Al * B
                mma16816(acc[0][2 * p],     al[0], bh[0], bh[2]);
                mma16816(acc[1][2 * p],     al[1], bh[0], bh[2]);
                mma16816(acc[0][2 * p + 1], al[0], bh[1], bh[3]);
                mma16816(acc[1][2 * p + 1], al[1], bh[1], bh[3]);
            }
        }
    };

    // --- prologue: fill stage 0 -------------------------------------------
    copyB(0, 0);
    CP_COMMIT();
    {
        float4 pv[4];
        loadA(pv, 0);
        stsA(0, pv);
    }

    // --- main pipeline -----------------------------------------------------
    #pragma unroll 1
    for (int i = 0; i < T; i++) {
        int s = i & 1;
        CP_WAIT0();
        __syncthreads();
        float4 pv2[4];
        if (i + 1 < T) {
            copyB(s ^ 1, (i + 1) * BK);
            CP_COMMIT();
            loadA(pv2, (i + 1) * BK);
        }
        compute(s);
        if (i + 1 < T) stsA(s ^ 1, pv2);
    }

    // --- epilogue: write rowscale * result --------------------------------
    #pragma unroll
    for (int mi = 0; mi < 2; mi++) {
        int r0 = m0 + wm + mi * 16 + g;
        float s0 = (r0 < M) ? __ldg(&rowscale[r0]) : 0.f;
        float s1 = (r0 + 8 < M) ? __ldg(&rowscale[r0 + 8]) : 0.f;
        #pragma unroll
        for (int ni = 0; ni < NF; ni++) {
            int c = wn + ni * 8 + 2 * tg;
            if (r0 < M)
                *(float2*)&C[(long)r0 * BN + c] =
                    make_float2(s0 * acc[mi][ni][0], s0 * acc[mi][ni][1]);
            if (r0 + 8 < M)
                *(float2*)&C[(long)(r0 + 8) * BN + c] =
                    make_float2(s1 * acc[mi][ni][2], s1 * acc[mi][ni][3]);
        }
    }
}

// ---------------------------------------------------------------------------
// CSR aggregation. pre rows are PRE-SCALED by dinv[src].
// out[d] = b + dinv[d]*(sum_s pre[s] + pre[d])
// DIM=128: warp per node. Dual accumulators, 2 edges/iter.
__global__ void k_agg128(const float* __restrict__ pre, const int* __restrict__ off,
                         const int* __restrict__ csr_src, const float* __restrict__ dinv,
                         const float* __restrict__ bias, float* __restrict__ out) {
    int t = blockIdx.x * blockDim.x + threadIdx.x;
    int node = t >> 5, lane = t & 31;
    if (node >= NN) return;
    int beg = __ldg(&off[node]), end = __ldg(&off[node + 1]);
    const float4* p4 = (const float4*)pre;
    float4 a0 = make_float4(0.f, 0.f, 0.f, 0.f);
    float4 a1 = make_float4(0.f, 0.f, 0.f, 0.f);
    int i = beg;
    for (; i + 1 < end; i += 2) {
        int s0 = __ldg(&csr_src[i]);
        int s1 = __ldg(&csr_src[i + 1]);
        float4 v0 = __ldg(p4 + (long)s0 * 32 + lane);
        float4 v1 = __ldg(p4 + (long)s1 * 32 + lane);
        a0.x += v0.x; a0.y += v0.y; a0.z += v0.z; a0.w += v0.w;
        a1.x += v1.x; a1.y += v1.y; a1.z += v1.z; a1.w += v1.w;
    }
    if (i < end) {
        int s0 = __ldg(&csr_src[i]);
        float4 v0 = __ldg(p4 + (long)s0 * 32 + lane);
        a0.x += v0.x; a0.y += v0.y; a0.z += v0.z; a0.w += v0.w;
    }
    float wd = __ldg(&dinv[node]);
    float4 sv = __ldg(p4 + (long)node * 32 + lane);
    float4 b = __ldg((const float4*)bias + lane);
    float4 o;
    o.x = b.x + wd * (a0.x + a1.x + sv.x);
    o.y = b.y + wd * (a0.y + a1.y + sv.y);
    o.z = b.z + wd * (a0.z + a1.z + sv.z);
    o.w = b.w + wd * (a0.w + a1.w + sv.w);
    *((float4*)out + (long)node * 32 + lane) = o;
}

// DIM=64: half-warp per node + FUSED heads GEMM. Dual accumulators.
__global__ void k_agg64h(const float* __restrict__ pre, const int* __restrict__ off,
                         const int* __restrict__ csr_src, const float* __restrict__ dinv,
                         const float* __restrict__ bias,
                         const float* __restrict__ W_attr, const float* __restrict__ W_attk,
                         float* __restrict__ out, float* __restrict__ headpre) {
    __shared__ float Ws[HH2 * 6];   // [k][c] layout
    for (int i = threadIdx.x; i < HH2 * 6; i += blockDim.x) {
        int k = i / 6, c = i % 6;
        Ws[i] = (c < 3) ? __ldg(&W_attr[k * 3 + c]) : __ldg(&W_attk[k * 3 + (c - 3)]);
    }
    __syncthreads();
    int t = blockIdx.x * blockDim.x + threadIdx.x;
    int node = t >> 4, lane = t & 15;
    if (node >= NN) return;
    int beg = __ldg(&off[node]), end = __ldg(&off[node + 1]);
    const float4* p4 = (const float4*)pre;
    float4 a0 = make_float4(0.f, 0.f, 0.f, 0.f);
    float4 a1 = make_float4(0.f, 0.f, 0.f, 0.f);
    int i = beg;
    for (; i + 1 < end; i += 2) {
        int s0 = __ldg(&csr_src[i]);
        int s1 = __ldg(&csr_src[i + 1]);
        float4 v0 = __ldg(p4 + (long)s0 * 16 + lane);
        float4 v1 = __ldg(p4 + (long)s1 * 16 + lane);
        a0.x += v0.x; a0.y += v0.y; a0.z += v0.z; a0.w += v0.w;
        a1.x += v1.x; a1.y += v1.y; a1.z += v1.z; a1.w += v1.w;
    }
    if (i < end) {
        int s0 = __ldg(&csr_src[i]);
        float4 v0 = __ldg(p4 + (long)s0 * 16 + lane);
        a0.x += v0.x; a0.y += v0.y; a0.z += v0.z; a0.w += v0.w;
    }
    float wd = __ldg(&dinv[node]);
    float4 sv = __ldg(p4 + (long)node * 16 + lane);
    float4 b = __ldg((const float4*)bias + lane);
    float4 o;
    o.x = b.x + wd * (a0.x + a1.x + sv.x);
    o.y = b.y + wd * (a0.y + a1.y + sv.y);
    o.z = b.z + wd * (a0.z + a1.z + sv.z);
    o.w = b.w + wd * (a0.w + a1.w + sv.w);
    *((float4*)out + (long)node * 16 + lane) = o;

    // heads: this lane holds features [4*lane, 4*lane+4) of the node's row
    int k0 = lane * 4;
    float h[6];
    #pragma unroll
    for (int c = 0; c < 6; c++)
        h[c] = o.x * Ws[(k0 + 0) * 6 + c] + o.y * Ws[(k0 + 1) * 6 + c]
             + o.z * Ws[(k0 + 2) * 6 + c] + o.w * Ws[(k0 + 3) * 6 + c];
    #pragma unroll
    for (int sh = 8; sh; sh >>= 1)
        #pragma unroll
        for (int c = 0; c < 6; c++)
            h[c] += __shfl_down_sync(0xffffffffu, h[c], sh, 16);
    if (lane == 0) {
        float2* hp = (float2*)(headpre + (long)node * 6);
        hp[0] = make_float2(wd * h[0], wd * h[1]);
        hp[1] = make_float2(wd * h[2], wd * h[3]);
        hp[2] = make_float2(wd * h[4], wd * h[5]);
    }
}

// DIM=6 heads + fused bias + log_softmax + att. pre rows pre-scaled.
__global__ void k_agg6(const float* __restrict__ pre, const int* __restrict__ off,
                       const int* __restrict__ csr_src, const float* __restrict__ dinv,
                       const float* __restrict__ b_attr, const float* __restrict__ b_attk,
                       float* __restrict__ out) {
    int t = blockIdx.x * blockDim.x + threadIdx.x;
    int node = t >> 5, lane = t & 31;
    if (node >= NN) return;
    int beg = __ldg(&off[node]), end = __ldg(&off[node + 1]);
    float a[6] = {0.f, 0.f, 0.f, 0.f, 0.f, 0.f};
    for (int i = beg + lane; i < end; i += 32) {
        int s = __ldg(&csr_src[i]);
        const float2* p = (const float2*)(pre + (long)s * 6);
        float2 p0 = __ldg(p), p1 = __ldg(p + 1), p2 = __ldg(p + 2);
        a[0] += p0.x; a[1] += p0.y;
        a[2] += p1.x; a[3] += p1.y;
        a[4] += p2.x; a[5] += p2.y;
    }
    #pragma unroll
    for (int o = 16; o; o >>= 1)
        #pragma unroll
        for (int c = 0; c < 6; c++) a[c] += __shfl_down_sync(0xffffffffu, a[c], o);
    if (lane == 0) {
        float wd = __ldg(&dinv[node]);
        const float2* p = (const float2*)(pre + (long)node * 6);
        float2 p0 = __ldg(p), p1 = __ldg(p + 1), p2 = __ldg(p + 2);
        float v0 = b_attr[0] + wd * (a[0] + p0.x);
        float v1 = b_attr[1] + wd * (a[1] + p0.y);
        float v2 = b_attr[2] + wd * (a[2] + p1.x);
        float v3 = b_attk[0] + wd * (a[3] + p1.y);
        float v4 = b_attk[1] + wd * (a[4] + p2.x);
        float v5 = b_attk[2] + wd * (a[5] + p2.y);
        float m = fmaxf(v0, fmaxf(v1, v2));
        float l = m + logf(expf(v0 - m) + expf(v1 - m) + expf(v2 - m));
        out[OUT_LSM + node * 3 + 0] = v0 - l;
        out[OUT_LSM + node * 3 + 1] = v1 - l;
        out[OUT_LSM + node * 3 + 2] = v2 - l;
        out[OUT_ATT + node * 3 + 0] = v3;
        out[OUT_ATT + node * 3 + 1] = v4;
        out[OUT_ATT + node * 3 + 2] = v5;
    }
}

// edge scores: res[e] = dot(feat[i], feat[j]), 8 lanes/edge
__global__ void k_edge_scores(const float* __restrict__ feat,
                              const int* __restrict__ pos,
                              const int* __restrict__ neg,
                              float* __restrict__ res) {
    int t = blockIdx.x * blockDim.x + threadIdx.x;
    int e = t >> 3, l = t & 7;
    if (e >= 2 * PEE) return;
    int a, b;
    if (e < PEE) { a = __ldg(pos + e); b = __ldg(pos + PEE + e); }
    else         { a = __ldg(neg + (e - PEE)); b = __ldg(neg + PEE + (e - PEE)); }
    const float4* fa = (const float4*)(feat + (long)a * 64);
    const float4* fb = (const float4*)(feat + (long)b * 64);
    float4 u = __ldg(fa + l), v = __ldg(fb + l);
    float s = u.x * v.x + u.y * v.y + u.z * v.z + u.w * v.w;
    u = __ldg(fa + l + 8); v = __ldg(fb + l + 8);
    s += u.x * v.x + u.y * v.y + u.z * v.z + u.w * v.w;
    s += __shfl_down_sync(0xffffffffu, s, 4, 8);
    s += __shfl_down_sync(0xffffffffu, s, 2, 8);
    s += __shfl_down_sync(0xffffffffu, s, 1, 8);
    if (l == 0) res[e] = s;
}

// ---------------------------------------------------------------------------
static inline int cdiv(long a, int b) { return (int)((a + b - 1) / b); }

// dynamic smem: (2*A + 1*B) per stage * 2 stages * 2 bytes
#define SMEM1 ((2 * 128 * 40 + 128 * 40) * 2 * 2)   // 61440
#define SMEM2 ((2 * 128 * 40 + 64 * 40) * 2 * 2)    // 51200

extern "C" void kernel_launch(void* const* d_in, const int* in_sizes, int n_in,
                              void* d_out, int out_size) {
    const float* x      = (const float*)d_in[0];
    const float* glove  = (const float*)d_in[1];
    const float* W1     = (const float*)d_in[2];
    const float* b1     = (const float*)d_in[3];
    const float* W2     = (const float*)d_in[4];
    const float* b2     = (const float*)d_in[5];
    const float* W_attr = (const float*)d_in[6];
    const float* b_attr = (const float*)d_in[7];
    const float* W_attk = (const float*)d_in[8];
    const float* b_attk = (const float*)d_in[9];
    const int* edge     = (const int*)d_in[10];
    const int* pos      = (const int*)d_in[11];
    const int* neg      = (const int*)d_in[12];
    float* out = (float*)d_out;

    const int* e_src = edge;
    const int* e_dst = edge + EE;

    int *degi, *off, *cursor, *csr_src;
    float *dinv, *gW1, *h1pre, *h1, *h2pre, *headpre;
    __half *W1T, *W2T;
    cudaGetSymbolAddress((void**)&degi,    g_degi);
    cudaGetSymbolAddress((void**)&dinv,    g_dinv);
    cudaGetSymbolAddress((void**)&off,     g_off);
    cudaGetSymbolAddress((void**)&cursor,  g_cursor);
    cudaGetSymbolAddress((void**)&csr_src, g_csr_src);
    cudaGetSymbolAddress((void**)&gW1,     g_gW1);
    cudaGetSymbolAddress((void**)&W1T,     g_W1T);
    cudaGetSymbolAddress((void**)&W2T,     g_W2T);
    cudaGetSymbolAddress((void**)&h1pre,   g_h1pre);
    cudaGetSymbolAddress((void**)&h1,      g_h1);
    cudaGetSymbolAddress((void**)&h2pre,   g_h2pre);
    cudaGetSymbolAddress((void**)&headpre, g_headpre);

    float* feat = out + OUT_FEAT;

    cudaFuncSetAttribute(k_mma<HH1, FF, KPAD1, false>,
                         cudaFuncAttributeMaxDynamicSharedMemorySize, SMEM1);
    cudaFuncSetAttribute(k_mma<HH2, HH1, KPAD2, true>,
                         cudaFuncAttributeMaxDynamicSharedMemorySize, SMEM2);

    cudaMemsetAsync(degi, 0, NN * sizeof(int));

    // degree/dinv first (GEMM epilogues consume dinv)
    k_deg_acc<<<cdiv(EE, 256), 256>>>(e_dst, degi);
    k_dinv<<<cdiv(NN, 256), 256>>>(degi, dinv);

    // weights prep
    k_glove_w1<<<FF, HH1>>>(glove, W1, gW1);
    k_splitW<FF, KPAD1, HH1><<<cdiv((long)HH1 * KPAD1, 256), 256>>>(gW1, W1T);

    // GEMM1: h1pre = dinv .* (x @ gW1)
    k_mma<HH1, FF, KPAD1, false><<<cdiv(NN, 128), 256, SMEM1>>>(x, W1T,
                                                                dinv, h1pre, NN);

    // CSR build
    k_scan<<<1, 1024>>>(degi, off, cursor);
    k_fill<<<cdiv(EE, 256), 256>>>(e_src, e_dst, cursor, csr_src);

    // layer 1 aggregate (bias + self-loop fused; rows pre-scaled)
    k_agg128<<<cdiv((long)NN * 32, 256), 256>>>(h1pre, off, csr_src, dinv, b1, h1);

    // GEMM2: h2pre = dinv .* (relu(h1) @ W2)
    k_splitW<KPAD2, KPAD2, HH2><<<cdiv((long)HH2 * KPAD2, 256), 256>>>(W2, W2T);
    k_mma<HH2, HH1, KPAD2, true><<<cdiv(NN, 128), 256, SMEM2>>>(h1, W2T,
                                                                dinv, h2pre, NN);

    // layer 2 aggregate + FUSED heads GEMM (headpre dinv-scaled on write)
    k_agg64h<<<cdiv((long)NN * 16, 256), 256>>>(h2pre, off, csr_src, dinv, b2,
                                                W_attr, W_attk, feat, headpre);

    // heads aggregate + log_softmax + att fused
    k_agg6<<<cdiv((long)NN * 32, 256), 256>>>(headpre, off, csr_src, dinv,
                                              b_attr, b_attk, out);

    // edge dot-product scores
    k_edge_scores<<<cdiv((long)2 * PEE * 8, 256), 256>>>(feat, pos, neg, out + OUT_RES);
}